// round 13
// baseline (speedup 1.0000x reference)
#include <cuda_runtime.h>

// streams [B=4, N=8, T=2048, D=1024] fp32, logits [8,8] fp32.
// out[b,i,t,d] = sum_j H[i,j] * streams[b,j,t,d], H = sinkhorn(logits), temp=1.
//
// Two kernels with Programmatic Dependent Launch (measured WIN R12):
//   sinkhorn_kernel (1 warp) -> trigger -> mix_kernel launches early, issues
//   its independent loads, then griddepsync before consuming d_H.
// R13 change: mix thread-coarsened x2 (16 front-batched LDG.128 per thread).

#define NS         8
#define SINK_ITERS 20
#define SINK_EPS   1e-8f
#define B_DIM      4
#define TD4        (2048 * 1024 / 4)   // float4 per (b,j) slice = 1<<19
#define TD4_LOG2   19

__device__ float d_H[NS * NS];

// ---------------------------------------------------------------------------
// Kernel 1: warp-parallel Sinkhorn. Lane l owns (row=l>>3, col=l&7) and
// (row+4, col). Row reduce: shfl_xor 1,2,4. Col reduce: e0+e1, shfl_xor 8,16.
// ---------------------------------------------------------------------------
__global__ void sinkhorn_kernel(const float* __restrict__ logits) {
    const unsigned FULL = 0xFFFFFFFFu;
    int lane = threadIdx.x;
    float x0 = logits[lane];
    float x1 = logits[lane + 32];

    float m0 = x0, m1 = x1;
    #pragma unroll
    for (int m = 1; m <= 4; m <<= 1) {
        m0 = fmaxf(m0, __shfl_xor_sync(FULL, m0, m));
        m1 = fmaxf(m1, __shfl_xor_sync(FULL, m1, m));
    }
    float p0 = expf(x0 - m0) + SINK_EPS;
    float p1 = expf(x1 - m1) + SINK_EPS;

    for (int it = 0; it < SINK_ITERS; it++) {
        float s0 = p0, s1 = p1;
        #pragma unroll
        for (int m = 1; m <= 4; m <<= 1) {
            s0 += __shfl_xor_sync(FULL, s0, m);
            s1 += __shfl_xor_sync(FULL, s1, m);
        }
        p0 = p0 / (s0 + SINK_EPS);
        p1 = p1 / (s1 + SINK_EPS);

        float c = p0 + p1;
        c += __shfl_xor_sync(FULL, c, 8);
        c += __shfl_xor_sync(FULL, c, 16);
        float inv = 1.0f / (c + SINK_EPS);
        p0 *= inv;
        p1 *= inv;
    }

    d_H[lane]      = p0;
    d_H[lane + 32] = p1;
    __threadfence();                               // publish before trigger
    cudaTriggerProgrammaticLaunchCompletion();     // let mix launch now
}

// ---------------------------------------------------------------------------
// Kernel 2: the mix, coarsened x2. Each thread owns two coalesced float4
// positions (pos, pos+256): 16 streaming loads issued before griddepsync,
// then 16 FMA-mixed streaming stores. Still 256MB read + 256MB write, 1x.
// ---------------------------------------------------------------------------
__global__ void __launch_bounds__(256)
mix_kernel(const float4* __restrict__ in, float4* __restrict__ out) {
    int pos0 = blockIdx.x * 512 + threadIdx.x;         // [0, B*TD4)
    int pos1 = pos0 + 256;

    int b0 = pos0 >> TD4_LOG2, r0 = pos0 & (TD4 - 1);
    int b1 = pos1 >> TD4_LOG2, r1 = pos1 & (TD4 - 1);
    int base0 = b0 * (NS * TD4) + r0;
    int base1 = b1 * (NS * TD4) + r1;

    // Independent of H: front-issue all 16 loads before the PDL wait.
    float4 v0[NS], v1[NS];
    #pragma unroll
    for (int j = 0; j < NS; j++) v0[j] = __ldcs(&in[base0 + j * TD4]);
    #pragma unroll
    for (int j = 0; j < NS; j++) v1[j] = __ldcs(&in[base1 + j * TD4]);

    // Wait for sinkhorn's published writes (no-op if kernels serialized).
    cudaGridDependencySynchronize();

    __shared__ float sH[NS * NS];
    if (threadIdx.x < NS * NS) sH[threadIdx.x] = d_H[threadIdx.x];
    __syncthreads();

    #pragma unroll
    for (int i = 0; i < NS; i++) {
        float4 a0 = make_float4(0.f, 0.f, 0.f, 0.f);
        float4 a1 = make_float4(0.f, 0.f, 0.f, 0.f);
        #pragma unroll
        for (int j = 0; j < NS; j++) {
            float h = sH[i * NS + j];
            a0.x = fmaf(h, v0[j].x, a0.x);
            a0.y = fmaf(h, v0[j].y, a0.y);
            a0.z = fmaf(h, v0[j].z, a0.z);
            a0.w = fmaf(h, v0[j].w, a0.w);
            a1.x = fmaf(h, v1[j].x, a1.x);
            a1.y = fmaf(h, v1[j].y, a1.y);
            a1.z = fmaf(h, v1[j].z, a1.z);
            a1.w = fmaf(h, v1[j].w, a1.w);
        }
        __stcs(&out[base0 + i * TD4], a0);
        __stcs(&out[base1 + i * TD4], a1);
    }
}

extern "C" void kernel_launch(void* const* d_in, const int* in_sizes, int n_in,
                              void* d_out, int out_size) {
    const float4* streams = (const float4*)d_in[0];
    const float*  logits  = (const float*)d_in[1];
    float4* out = (float4*)d_out;

    sinkhorn_kernel<<<1, 32>>>(logits);

    // Mix with programmatic dependent launch: overlaps its block launch +
    // load prologue with the sinkhorn kernel.
    cudaLaunchConfig_t cfg = {};
    cfg.gridDim  = dim3((B_DIM * TD4) / 512);   // 4096 blocks, 2 float4/thread
    cfg.blockDim = dim3(256);
    cfg.dynamicSmemBytes = 0;
    cfg.stream = 0;

    cudaLaunchAttribute attrs[1];
    attrs[0].id = cudaLaunchAttributeProgrammaticStreamSerialization;
    attrs[0].val.programmaticStreamSerializationAllowed = 1;
    cfg.attrs = attrs;
    cfg.numAttrs = 1;

    cudaLaunchKernelEx(&cfg, mix_kernel, streams, out);
}